// round 3
// baseline (speedup 1.0000x reference)
#include <cuda_runtime.h>

#define DM 1024
#define NH 16
#define DK 64
#define S_LEN 2048
#define MAXROWS (4*2048)

// Scratch: device globals (no allocation allowed in kernel_launch)
__device__ float g_Q[(size_t)MAXROWS*DM];
__device__ float g_K[(size_t)MAXROWS*DM];
__device__ float g_V[(size_t)MAXROWS*DM];
__device__ float g_A[(size_t)MAXROWS*DM];

// ---------------------------------------------------------------------------
// C[M,N] = A[M,K] * B[N,K]^T   (both row-major, K contiguous)
// 128x128 block tile, K-tile 8, 256 threads, 8x8 per-thread micro-tile.
// ---------------------------------------------------------------------------
__global__ __launch_bounds__(256)
void sgemm_nt(const float* __restrict__ A, const float* __restrict__ B,
              float* __restrict__ C, int M, int N, int K)
{
    __shared__ float As[8][132];
    __shared__ float Bs[8][132];
    const int tid = threadIdx.x;
    const int tx = tid & 15, ty = tid >> 4;
    const int m0 = blockIdx.y * 128, n0 = blockIdx.x * 128;
    const int lrow = tid >> 1;
    const int lk   = (tid & 1) * 4;

    float acc[8][8];
#pragma unroll
    for (int i = 0; i < 8; i++)
#pragma unroll
        for (int j = 0; j < 8; j++) acc[i][j] = 0.f;

    const float* Ap = A + (size_t)(m0 + lrow) * K + lk;
    const float* Bp = B + (size_t)(n0 + lrow) * K + lk;

    for (int k0 = 0; k0 < K; k0 += 8) {
        float4 a4 = *(const float4*)(Ap + k0);
        float4 b4 = *(const float4*)(Bp + k0);
        As[lk+0][lrow] = a4.x; As[lk+1][lrow] = a4.y;
        As[lk+2][lrow] = a4.z; As[lk+3][lrow] = a4.w;
        Bs[lk+0][lrow] = b4.x; Bs[lk+1][lrow] = b4.y;
        Bs[lk+2][lrow] = b4.z; Bs[lk+3][lrow] = b4.w;
        __syncthreads();
#pragma unroll
        for (int k = 0; k < 8; k++) {
            float4 a0 = *(const float4*)&As[k][ty*8];
            float4 a1 = *(const float4*)&As[k][ty*8+4];
            float4 b0 = *(const float4*)&Bs[k][tx*8];
            float4 b1 = *(const float4*)&Bs[k][tx*8+4];
            float av[8] = {a0.x,a0.y,a0.z,a0.w,a1.x,a1.y,a1.z,a1.w};
            float bv[8] = {b0.x,b0.y,b0.z,b0.w,b1.x,b1.y,b1.z,b1.w};
#pragma unroll
            for (int i = 0; i < 8; i++)
#pragma unroll
                for (int j = 0; j < 8; j++) acc[i][j] += av[i]*bv[j];
        }
        __syncthreads();
    }

#pragma unroll
    for (int i = 0; i < 8; i++) {
        float* Cp = C + (size_t)(m0 + ty*8 + i) * N + n0 + tx*8;
        *(float4*)(Cp)   = make_float4(acc[i][0],acc[i][1],acc[i][2],acc[i][3]);
        *(float4*)(Cp+4) = make_float4(acc[i][4],acc[i][5],acc[i][6],acc[i][7]);
    }
}

// ---------------------------------------------------------------------------
// Swizzled 64x64 fp32 smem tile helpers: float4-granular XOR swizzle makes all
// LDS.128/STS.128 phases bank-conflict-free (padding cannot: rows step by 4
// float4s so pad*4 mod 32 can never generate the full bank spread).
// ---------------------------------------------------------------------------
__device__ __forceinline__ int sw4(int row, int col4) {
    return row*64 + ((col4 ^ ((row >> 2) & 7)) << 2);
}
__device__ __forceinline__ float4 ld4sw(const float* b, int row, int col) {
    return *(const float4*)(b + sw4(row, col >> 2));
}
__device__ __forceinline__ void st4sw(float* b, int row, int col, float4 v) {
    *(float4*)(b + sw4(row, col >> 2)) = v;
}
__device__ __forceinline__ int swidx(int row, int col) {
    return sw4(row, col >> 2) | (col & 3);
}

// ---------------------------------------------------------------------------
// Flash attention: 1 CTA = 64 queries of one (b,h). Online softmax over 64-wide
// KV tiles. Qs/Ks/Vs = 3 x 16KB = 48KB static smem; Ks reused to hold P.
// Thread (ty,tx): rows ty*4..+3, cols tx*4..+3 (16x16 thread grid).
// ---------------------------------------------------------------------------
__global__ __launch_bounds__(256)
void attn_kernel(const float* __restrict__ Qg, const float* __restrict__ Kg,
                 const float* __restrict__ Vg, float* __restrict__ Og, int S)
{
    __shared__ float Qs[64*64];
    __shared__ float Ks[64*64];   // reused as P after QK^T
    __shared__ float Vs[64*64];
    const int tid = threadIdx.x;
    const int tx = tid & 15, ty = tid >> 4;
    const int b = blockIdx.z, h = blockIdx.y;
    const int q0 = blockIdx.x * 64;
    const size_t base = ((size_t)b * S) * DM + h * DK;
    const float scale = 0.125f;   // 1/sqrt(64)

#pragma unroll
    for (int t = 0; t < 4; t++) {
        int idx = tid + t*256;
        int r = idx >> 4, c4 = (idx & 15) << 2;
        float4 v = *(const float4*)(Qg + base + (size_t)(q0 + r)*DM + c4);
        v.x *= scale; v.y *= scale; v.z *= scale; v.w *= scale;
        st4sw(Qs, r, c4, v);
    }

    float m[4], l[4], acc[4][4];
#pragma unroll
    for (int i = 0; i < 4; i++) {
        m[i] = -1e30f; l[i] = 0.f;
#pragma unroll
        for (int c = 0; c < 4; c++) acc[i][c] = 0.f;
    }

    for (int kv0 = 0; kv0 < S; kv0 += 64) {
        __syncthreads();   // previous PV done reading Ks/Vs (and Qs store on iter 0)
#pragma unroll
        for (int t = 0; t < 4; t++) {
            int idx = tid + t*256;
            int r = idx >> 4, c4 = (idx & 15) << 2;
            size_t g = base + (size_t)(kv0 + r)*DM + c4;
            st4sw(Ks, r, c4, *(const float4*)(Kg + g));
            st4sw(Vs, r, c4, *(const float4*)(Vg + g));
        }
        __syncthreads();

        // S = Q K^T  (per-thread 4x4, vectorized over d)
        float s[4][4];
#pragma unroll
        for (int i = 0; i < 4; i++)
#pragma unroll
            for (int j = 0; j < 4; j++) s[i][j] = 0.f;

#pragma unroll
        for (int d = 0; d < 64; d += 4) {
            float4 qv[4], kv[4];
#pragma unroll
            for (int i = 0; i < 4; i++) qv[i] = ld4sw(Qs, ty*4 + i, d);
#pragma unroll
            for (int j = 0; j < 4; j++) kv[j] = ld4sw(Ks, tx*4 + j, d);
#pragma unroll
            for (int i = 0; i < 4; i++)
#pragma unroll
                for (int j = 0; j < 4; j++)
                    s[i][j] += qv[i].x*kv[j].x + qv[i].y*kv[j].y
                             + qv[i].z*kv[j].z + qv[i].w*kv[j].w;
        }
        __syncthreads();   // all done reading Ks -> safe to overwrite with P

        // Online softmax: row stats live in the 16 lanes sharing ty (xor-shfl, width 16)
#pragma unroll
        for (int i = 0; i < 4; i++) {
            float rm = fmaxf(fmaxf(s[i][0], s[i][1]), fmaxf(s[i][2], s[i][3]));
#pragma unroll
            for (int off = 8; off > 0; off >>= 1)
                rm = fmaxf(rm, __shfl_xor_sync(0xffffffffu, rm, off, 16));
            float mn = fmaxf(m[i], rm);
            float alpha = __expf(m[i] - mn);
            float ssum = 0.f;
#pragma unroll
            for (int j = 0; j < 4; j++) {
                float p = __expf(s[i][j] - mn);
                ssum += p;
                Ks[swidx(ty*4 + i, tx*4 + j)] = p;
            }
#pragma unroll
            for (int off = 8; off > 0; off >>= 1)
                ssum += __shfl_xor_sync(0xffffffffu, ssum, off, 16);
            l[i] = l[i]*alpha + ssum;
            m[i] = mn;
#pragma unroll
            for (int c = 0; c < 4; c++) acc[i][c] *= alpha;
        }
        __syncthreads();   // P visible to all

        // O += P * V
#pragma unroll 4
        for (int j = 0; j < 64; j++) {
            float4 vv = ld4sw(Vs, j, tx*4);
            float pv[4];
#pragma unroll
            for (int i = 0; i < 4; i++) pv[i] = Ks[swidx(ty*4 + i, j)];
#pragma unroll
            for (int i = 0; i < 4; i++) {
                acc[i][0] += pv[i]*vv.x;
                acc[i][1] += pv[i]*vv.y;
                acc[i][2] += pv[i]*vv.z;
                acc[i][3] += pv[i]*vv.w;
            }
        }
    }

#pragma unroll
    for (int i = 0; i < 4; i++) {
        float inv = 1.f / l[i];
        float4 o = make_float4(acc[i][0]*inv, acc[i][1]*inv,
                               acc[i][2]*inv, acc[i][3]*inv);
        *(float4*)(Og + base + (size_t)(q0 + ty*4 + i)*DM + tx*4) = o;
    }
}

// ---------------------------------------------------------------------------
extern "C" void kernel_launch(void* const* d_in, const int* in_sizes, int n_in,
                              void* d_out, int out_size)
{
    const float* query = (const float*)d_in[0];
    const float* key   = (const float*)d_in[1];
    const float* value = (const float*)d_in[2];
    const float* W_q   = (const float*)d_in[3];
    const float* W_k   = (const float*)d_in[4];
    const float* W_v   = (const float*)d_in[5];
    const float* W_o   = (const float*)d_in[6];

    const int BS = in_sizes[0] / DM;   // B*S (8192)
    const int S  = S_LEN;
    const int B  = BS / S;

    float *q, *k, *v, *a;
    cudaGetSymbolAddress((void**)&q, g_Q);
    cudaGetSymbolAddress((void**)&k, g_K);
    cudaGetSymbolAddress((void**)&v, g_V);
    cudaGetSymbolAddress((void**)&a, g_A);

    dim3 gp(DM/128, BS/128);
    sgemm_nt<<<gp, 256>>>(query, W_q, q, BS, DM, DM);
    sgemm_nt<<<gp, 256>>>(key,   W_k, k, BS, DM, DM);
    sgemm_nt<<<gp, 256>>>(value, W_v, v, BS, DM, DM);

    dim3 ga(S/64, NH, B);
    attn_kernel<<<ga, 256>>>(q, k, v, a, S);

    sgemm_nt<<<gp, 256>>>(a, W_o, (float*)d_out, BS, DM, DM);
}

// round 6
// speedup vs baseline: 1.4563x; 1.4563x over previous
#include <cuda_runtime.h>
#include <cuda_bf16.h>
#include <cstdint>

#define DM 1024
#define NH 16
#define DK 64
#define S_LEN 2048
#define MAXROWS (4*2048)
#define KSPLIT (3*DM)   // 3072

// Scratch: device globals (no allocation allowed in kernel_launch)
__device__ float g_Q[(size_t)MAXROWS*DM];
__device__ float g_K[(size_t)MAXROWS*DM];
__device__ float g_V[(size_t)MAXROWS*DM];
__device__ float g_A[(size_t)MAXROWS*DM];
__device__ __nv_bfloat16 g_Asp[(size_t)MAXROWS*KSPLIT];  // [hi | hi | lo]
__device__ __nv_bfloat16 g_Wsp[(size_t)DM*KSPLIT];       // [hi | lo | hi]

// ===========================================================================
// PTX helpers (sm_80-era: cp.async / ldmatrix / mma.sync — valid on sm_103 base)
// ===========================================================================
__device__ __forceinline__ uint32_t smem_u32(const void* p) {
    return (uint32_t)__cvta_generic_to_shared(p);
}
__device__ __forceinline__ void cp_async16(uint32_t dst, const void* src) {
    asm volatile("cp.async.cg.shared.global [%0], [%1], 16;\n" :: "r"(dst), "l"(src));
}
__device__ __forceinline__ void cp_commit() {
    asm volatile("cp.async.commit_group;\n");
}
__device__ __forceinline__ void cp_wait1() {
    asm volatile("cp.async.wait_group 1;\n");
}
__device__ __forceinline__ void cp_wait0() {
    asm volatile("cp.async.wait_group 0;\n");
}
__device__ __forceinline__ void ldm_x4(uint32_t* r, uint32_t addr) {
    asm volatile("ldmatrix.sync.aligned.m8n8.x4.shared.b16 {%0,%1,%2,%3}, [%4];\n"
        : "=r"(r[0]), "=r"(r[1]), "=r"(r[2]), "=r"(r[3]) : "r"(addr));
}
__device__ __forceinline__ void mma_bf16(float* d, const uint32_t* a, const uint32_t* b) {
    asm volatile(
        "mma.sync.aligned.m16n8k16.row.col.f32.bf16.bf16.f32 "
        "{%0,%1,%2,%3}, {%4,%5,%6,%7}, {%8,%9}, {%0,%1,%2,%3};\n"
        : "+f"(d[0]), "+f"(d[1]), "+f"(d[2]), "+f"(d[3])
        : "r"(a[0]), "r"(a[1]), "r"(a[2]), "r"(a[3]), "r"(b[0]), "r"(b[1]));
}

// ===========================================================================
// Split fp32 -> bf16 hi/lo, concatenated along K (3 segments of DM).
// lo_off = 2048 for A-side ([hi|hi|lo]); lo_off = 1024 for B-side ([hi|lo|hi]).
// Sum over K' = Ahi*Bhi + Ahi*Blo + Alo*Bhi.
// ===========================================================================
__global__ __launch_bounds__(256)
void split_kernel(const float* __restrict__ X, __nv_bfloat16* __restrict__ Y, int lo_off)
{
    int idx4 = blockIdx.x * 256 + threadIdx.x;   // one float4 per thread
    int r = idx4 >> 8;            // 256 float4 per 1024-wide row
    int c = (idx4 & 255) << 2;
    float4 x = *(const float4*)(X + (size_t)r * DM + c);
    float xs[4] = {x.x, x.y, x.z, x.w};
    __nv_bfloat16 hi[4], lo[4];
#pragma unroll
    for (int j = 0; j < 4; j++) {
        hi[j] = __float2bfloat16(xs[j]);
        lo[j] = __float2bfloat16(xs[j] - __bfloat162float(hi[j]));
    }
    const int hi2_off = (lo_off == 2048) ? 1024 : 2048;
    __nv_bfloat16* row = Y + (size_t)r * KSPLIT;
    __nv_bfloat162* h0 = (__nv_bfloat162*)(row + c);
    __nv_bfloat162* h1 = (__nv_bfloat162*)(row + hi2_off + c);
    __nv_bfloat162* l0 = (__nv_bfloat162*)(row + lo_off + c);
    h0[0] = __halves2bfloat162(hi[0], hi[1]); h0[1] = __halves2bfloat162(hi[2], hi[3]);
    h1[0] = __halves2bfloat162(hi[0], hi[1]); h1[1] = __halves2bfloat162(hi[2], hi[3]);
    l0[0] = __halves2bfloat162(lo[0], lo[1]); l0[1] = __halves2bfloat162(lo[2], lo[3]);
}

// ===========================================================================
// C[M,N] = A[M,K] * B[N,K]^T  via mma.sync bf16 (fp32 accum in regs).
// CTA tile 128x128, BK=64, 8 warps (2x4), warp tile 64x32.
// SMEM: 128B rows (64 bf16), XOR swizzle chunk ^= row&7 -> ldmatrix conflict-free.
// Double-buffered cp.async.
// ===========================================================================
#define G_SMEM_BYTES (2 * (128*64 + 128*64) * 2)   // 65536

__global__ __launch_bounds__(256)
void gemm_hmma(const __nv_bfloat16* __restrict__ A, const __nv_bfloat16* __restrict__ B,
               float* __restrict__ C, int M, int N, int K)
{
    extern __shared__ char smem[];
    const uint32_t sbase = smem_u32(smem);
    const int tid = threadIdx.x;
    const int wid = tid >> 5, lane = tid & 31;
    const int m0 = blockIdx.y * 128, n0 = blockIdx.x * 128;
    const int wm = (wid & 1) * 64, wn = (wid >> 1) * 32;

    const uint32_t BUF = 128*64*2*2;             // 32768 bytes per buffer (A+B)
    const uint32_t AOFF = 0, BOFF = 128*64*2;    // B tile after A tile

    // loader coords: 8 chunks (16B) per thread per tile side is 4+4
    const int lc  = tid & 7;        // chunk col 0..7 (x16B)
    const int lr  = tid >> 3;       // row base 0..31
    const uint32_t lsw = (uint32_t)((lc ^ (lr & 7)) << 4);

    float acc[4][4][4];
#pragma unroll
    for (int mf = 0; mf < 4; mf++)
#pragma unroll
        for (int nf = 0; nf < 4; nf++)
#pragma unroll
            for (int j = 0; j < 4; j++) acc[mf][nf][j] = 0.f;

    // per-lane ldmatrix invariants
    const int lmat = lane >> 3, rlo = lane & 7;
    const int rA   = wm + (lmat & 1) * 8 + rlo;   // A row (const per lane)
    const int selA = lmat >> 1;                   // A chunk offset
    const int nB   = wn + (lmat >> 1) * 8 + rlo;  // B row
    const int selB = lmat & 1;

    const int iters = K >> 6;

    // ---- preload tile 0
    {
        const __nv_bfloat16* Ak = A + (size_t)m0 * K;
        const __nv_bfloat16* Bk = B + (size_t)n0 * K;
#pragma unroll
        for (int t = 0; t < 4; t++) {
            int r = lr + t * 32;
            cp_async16(sbase + AOFF + (uint32_t)r * 128 + lsw, Ak + (size_t)r * K + lc * 8);
            cp_async16(sbase + BOFF + (uint32_t)r * 128 + lsw, Bk + (size_t)r * K + lc * 8);
        }
        cp_commit();
    }

    for (int it = 0; it < iters; ++it) {
        const int buf = it & 1;
        if (it + 1 < iters) {
            const uint32_t dA = sbase + (buf ^ 1) * BUF + AOFF;
            const uint32_t dB = sbase + (buf ^ 1) * BUF + BOFF;
            const __nv_bfloat16* Ak = A + (size_t)m0 * K + (it + 1) * 64;
            const __nv_bfloat16* Bk = B + (size_t)n0 * K + (it + 1) * 64;
#pragma unroll
            for (int t = 0; t < 4; t++) {
                int r = lr + t * 32;
                cp_async16(dA + (uint32_t)r * 128 + lsw, Ak + (size_t)r * K + lc * 8);
                cp_async16(dB + (uint32_t)r * 128 + lsw, Bk + (size_t)r * K + lc * 8);
            }
            cp_commit();
            cp_wait1();
        } else {
            cp_wait0();
        }
        __syncthreads();

        const uint32_t aS = sbase + buf * BUF + AOFF;
        const uint32_t bS = sbase + buf * BUF + BOFF;
#pragma unroll
        for (int kk = 0; kk < 4; kk++) {
            uint32_t a[4][4], b[2][4];
            const uint32_t ca = (uint32_t)(((kk * 2 + selA) ^ (rA & 7)) << 4);
#pragma unroll
            for (int mf = 0; mf < 4; mf++)
                ldm_x4(a[mf], aS + (uint32_t)(rA + mf * 16) * 128 + ca);
            const uint32_t cb = (uint32_t)(((kk * 2 + selB) ^ (nB & 7)) << 4);
#pragma unroll
            for (int nf2 = 0; nf2 < 2; nf2++)
                ldm_x4(b[nf2], bS + (uint32_t)(nB + nf2 * 16) * 128 + cb);
#pragma unroll
            for (int mf = 0; mf < 4; mf++)
#pragma unroll
                for (int nf = 0; nf < 4; nf++)
                    mma_bf16(acc[mf][nf], a[mf], b[nf >> 1] + (nf & 1) * 2);
        }
        __syncthreads();
    }

    // ---- epilogue: fragment layout -> direct float2 stores
    const int er = lane >> 2, ec = (lane & 3) * 2;
#pragma unroll
    for (int mf = 0; mf < 4; mf++) {
        const int r0 = m0 + wm + mf * 16 + er;
#pragma unroll
        for (int nf = 0; nf < 4; nf++) {
            const int c = n0 + wn + nf * 8 + ec;
            *(float2*)(C + (size_t)r0 * N + c)       = make_float2(acc[mf][nf][0], acc[mf][nf][1]);
            *(float2*)(C + (size_t)(r0 + 8) * N + c) = make_float2(acc[mf][nf][2], acc[mf][nf][3]);
        }
    }
}

// ===========================================================================
// Swizzled 64x64 fp32 smem tile helpers (attention)
// ===========================================================================
__device__ __forceinline__ int sw4(int row, int col4) {
    return row*64 + ((col4 ^ ((row >> 2) & 7)) << 2);
}
__device__ __forceinline__ float4 ld4sw(const float* b, int row, int col) {
    return *(const float4*)(b + sw4(row, col >> 2));
}
__device__ __forceinline__ void st4sw(float* b, int row, int col, float4 v) {
    *(float4*)(b + sw4(row, col >> 2)) = v;
}
__device__ __forceinline__ int swidx(int row, int col) {
    return sw4(row, col >> 2) | (col & 3);
}

// ---------------------------------------------------------------------------
// Flash attention: 1 CTA = 64 queries of one (b,h). fp32, online softmax.
// ---------------------------------------------------------------------------
__global__ __launch_bounds__(256)
void attn_kernel(const float* __restrict__ Qg, const float* __restrict__ Kg,
                 const float* __restrict__ Vg, float* __restrict__ Og, int S)
{
    __shared__ float Qs[64*64];
    __shared__ float Ks[64*64];   // reused as P after QK^T
    __shared__ float Vs[64*64];
    const int tid = threadIdx.x;
    const int tx = tid & 15, ty = tid >> 4;
    const int b = blockIdx.z, h = blockIdx.y;
    const int q0 = blockIdx.x * 64;
    const size_t base = ((size_t)b * S) * DM + h * DK;
    const float scale = 0.125f;

#pragma unroll
    for (int t = 0; t < 4; t++) {
        int idx = tid + t*256;
        int r = idx >> 4, c4 = (idx & 15) << 2;
        float4 v = *(const float4*)(Qg + base + (size_t)(q0 + r)*DM + c4);
        v.x *= scale; v.y *= scale; v.z *= scale; v.w *= scale;
        st4sw(Qs, r, c4, v);
    }

    float m[4], l[4], acc[4][4];
#pragma unroll
    for (int i = 0; i < 4; i++) {
        m[i] = -1e30f; l[i] = 0.f;
#pragma unroll
        for (int c = 0; c < 4; c++) acc[i][c] = 0.f;
    }

    for (int kv0 = 0; kv0 < S; kv0 += 64) {
        __syncthreads();
#pragma unroll
        for (int t = 0; t < 4; t++) {
            int idx = tid + t*256;
            int r = idx >> 4, c4 = (idx & 15) << 2;
            size_t g = base + (size_t)(kv0 + r)*DM + c4;
            st4sw(Ks, r, c4, *(const float4*)(Kg + g));
            st4sw(Vs, r, c4, *(const float4*)(Vg + g));
        }
        __syncthreads();

        float s[4][4];
#pragma unroll
        for (int i = 0; i < 4; i++)
#pragma unroll
            for (int j = 0; j < 4; j++) s[i][j] = 0.f;

#pragma unroll
        for (int d = 0; d < 64; d += 4) {
            float4 qv[4], kv[4];
#pragma unroll
            for (int i = 0; i < 4; i++) qv[i] = ld4sw(Qs, ty*4 + i, d);
#pragma unroll
            for (int j = 0; j < 4; j++) kv[j] = ld4sw(Ks, tx*4 + j, d);
#pragma unroll
            for (int i = 0; i < 4; i++)
#pragma unroll
                for (int j = 0; j < 4; j++)
                    s[i][j] += qv[i].x*kv[j].x + qv[i].y*kv[j].y
                             + qv[i].z*kv[j].z + qv[i].w*kv[j].w;
        }
        __syncthreads();

#pragma unroll
        for (int i = 0; i < 4; i++) {
            float rm = fmaxf(fmaxf(s[i][0], s[i][1]), fmaxf(s[i][2], s[i][3]));
#pragma unroll
            for (int off = 8; off > 0; off >>= 1)
                rm = fmaxf(rm, __shfl_xor_sync(0xffffffffu, rm, off, 16));
            float mn = fmaxf(m[i], rm);
            float alpha = __expf(m[i] - mn);
            float ssum = 0.f;
#pragma unroll
            for (int j = 0; j < 4; j++) {
                float p = __expf(s[i][j] - mn);
                ssum += p;
                Ks[swidx(ty*4 + i, tx*4 + j)] = p;
            }
#pragma unroll
            for (int off = 8; off > 0; off >>= 1)
                ssum += __shfl_xor_sync(0xffffffffu, ssum, off, 16);
            l[i] = l[i]*alpha + ssum;
            m[i] = mn;
#pragma unroll
            for (int c = 0; c < 4; c++) acc[i][c] *= alpha;
        }
        __syncthreads();

#pragma unroll 4
        for (int j = 0; j < 64; j++) {
            float4 vv = ld4sw(Vs, j, tx*4);
            float pv[4];
#pragma unroll
            for (int i = 0; i < 4; i++) pv[i] = Ks[swidx(ty*4 + i, j)];
#pragma unroll
            for (int i = 0; i < 4; i++) {
                acc[i][0] += pv[i]*vv.x;
                acc[i][1] += pv[i]*vv.y;
                acc[i][2] += pv[i]*vv.z;
                acc[i][3] += pv[i]*vv.w;
            }
        }
    }

#pragma unroll
    for (int i = 0; i < 4; i++) {
        float inv = 1.f / l[i];
        float4 o = make_float4(acc[i][0]*inv, acc[i][1]*inv,
                               acc[i][2]*inv, acc[i][3]*inv);
        *(float4*)(Og + base + (size_t)(q0 + ty*4 + i)*DM + tx*4) = o;
    }
}

// ===========================================================================
extern "C" void kernel_launch(void* const* d_in, const int* in_sizes, int n_in,
                              void* d_out, int out_size)
{
    const float* query = (const float*)d_in[0];
    const float* key   = (const float*)d_in[1];
    const float* value = (const float*)d_in[2];
    const float* W_q   = (const float*)d_in[3];
    const float* W_k   = (const float*)d_in[4];
    const float* W_v   = (const float*)d_in[5];
    const float* W_o   = (const float*)d_in[6];

    const int BS = in_sizes[0] / DM;   // B*S = 8192
    const int S  = S_LEN;
    const int B  = BS / S;

    float *q, *k, *v, *a;
    __nv_bfloat16 *asp, *wsp;
    cudaGetSymbolAddress((void**)&q,   g_Q);
    cudaGetSymbolAddress((void**)&k,   g_K);
    cudaGetSymbolAddress((void**)&v,   g_V);
    cudaGetSymbolAddress((void**)&a,   g_A);
    cudaGetSymbolAddress((void**)&asp, g_Asp);
    cudaGetSymbolAddress((void**)&wsp, g_Wsp);

    cudaFuncSetAttribute(gemm_hmma, cudaFuncAttributeMaxDynamicSharedMemorySize,
                         G_SMEM_BYTES);

    const dim3 gg(DM/128, BS/128);   // (8, 64)
    const int actBlocks = BS;        // BS rows * 256 float4/row / 256 thr
    const int wBlocks   = DM;

    // Q = query @ Wq^T
    split_kernel<<<actBlocks, 256>>>(query, asp, 2048);
    split_kernel<<<wBlocks,   256>>>(W_q,   wsp, 1024);
    gemm_hmma<<<gg, 256, G_SMEM_BYTES>>>(asp, wsp, q, BS, DM, KSPLIT);
    // K
    split_kernel<<<actBlocks, 256>>>(key, asp, 2048);
    split_kernel<<<wBlocks,   256>>>(W_k, wsp, 1024);
    gemm_hmma<<<gg, 256, G_SMEM_BYTES>>>(asp, wsp, k, BS, DM, KSPLIT);
    // V
    split_kernel<<<actBlocks, 256>>>(value, asp, 2048);
    split_kernel<<<wBlocks,   256>>>(W_v,   wsp, 1024);
    gemm_hmma<<<gg, 256, G_SMEM_BYTES>>>(asp, wsp, v, BS, DM, KSPLIT);

    // attention (fp32)
    dim3 ga(S/64, NH, B);
    attn_kernel<<<ga, 256>>>(q, k, v, a, S);

    // out = attn @ Wo^T
    split_kernel<<<actBlocks, 256>>>(a,   asp, 2048);
    split_kernel<<<wBlocks,   256>>>(W_o, wsp, 1024);
    gemm_hmma<<<gg, 256, G_SMEM_BYTES>>>(asp, wsp, (float*)d_out, BS, DM, KSPLIT);
}

// round 7
// speedup vs baseline: 3.0697x; 2.1079x over previous
#include <cuda_runtime.h>
#include <cuda_bf16.h>
#include <cstdint>

#define DM 1024
#define NH 16
#define DK 64
#define S_LEN 2048
#define MAXROWS (4*2048)
#define KSPLIT (3*DM)   // 3072

typedef __nv_bfloat16 bf16;

// Scratch: device globals (no allocation allowed in kernel_launch)
__device__ float g_Q[(size_t)MAXROWS*DM];
__device__ float g_K[(size_t)MAXROWS*DM];
__device__ float g_V[(size_t)MAXROWS*DM];
__device__ float g_A[(size_t)MAXROWS*DM];
__device__ bf16 g_Asp[(size_t)MAXROWS*KSPLIT];  // [hi | hi | lo]
__device__ bf16 g_Wsp[(size_t)DM*KSPLIT];       // [hi | lo | hi]
__device__ bf16 g_Qh[(size_t)MAXROWS*DM];
__device__ bf16 g_Ql[(size_t)MAXROWS*DM];
__device__ bf16 g_Kh[(size_t)MAXROWS*DM];
__device__ bf16 g_Kl[(size_t)MAXROWS*DM];
__device__ bf16 g_Vth[(size_t)MAXROWS*DM];      // [b][h][d 64][S] hi
__device__ bf16 g_Vtl[(size_t)MAXROWS*DM];      // lo

// ===========================================================================
// PTX helpers (sm_80-era: cp.async / ldmatrix / mma.sync — valid on sm_103 base)
// ===========================================================================
__device__ __forceinline__ uint32_t smem_u32(const void* p) {
    return (uint32_t)__cvta_generic_to_shared(p);
}
__device__ __forceinline__ void cp_async16(uint32_t dst, const void* src) {
    asm volatile("cp.async.cg.shared.global [%0], [%1], 16;\n" :: "r"(dst), "l"(src));
}
__device__ __forceinline__ void cp_commit() {
    asm volatile("cp.async.commit_group;\n");
}
__device__ __forceinline__ void cp_wait1() {
    asm volatile("cp.async.wait_group 1;\n");
}
__device__ __forceinline__ void cp_wait0() {
    asm volatile("cp.async.wait_group 0;\n");
}
__device__ __forceinline__ void ldm_x4(uint32_t* r, uint32_t addr) {
    asm volatile("ldmatrix.sync.aligned.m8n8.x4.shared.b16 {%0,%1,%2,%3}, [%4];\n"
        : "=r"(r[0]), "=r"(r[1]), "=r"(r[2]), "=r"(r[3]) : "r"(addr));
}
__device__ __forceinline__ void mma_bf16(float* d, const uint32_t* a, const uint32_t* b) {
    asm volatile(
        "mma.sync.aligned.m16n8k16.row.col.f32.bf16.bf16.f32 "
        "{%0,%1,%2,%3}, {%4,%5,%6,%7}, {%8,%9}, {%0,%1,%2,%3};\n"
        : "+f"(d[0]), "+f"(d[1]), "+f"(d[2]), "+f"(d[3])
        : "r"(a[0]), "r"(a[1]), "r"(a[2]), "r"(a[3]), "r"(b[0]), "r"(b[1]));
}
// ldmatrix on a 64-bf16-wide (128B) swizzled tile: A-operand mapping (rows=m, chunks=k)
__device__ __forceinline__ void ldmA(uint32_t* r, uint32_t tbase, int R0, int kk, int lane) {
    const int lmat = lane >> 3, rlo = lane & 7;
    const int row = R0 + (lmat & 1) * 8 + rlo;
    const int ch  = kk * 2 + (lmat >> 1);
    ldm_x4(r, tbase + (uint32_t)row * 128 + (uint32_t)((ch ^ (row & 7)) << 4));
}
// B-operand mapping (rows=n, chunks=k)
__device__ __forceinline__ void ldmB(uint32_t* r, uint32_t tbase, int R0, int kk, int lane) {
    const int lmat = lane >> 3, rlo = lane & 7;
    const int row = R0 + (lmat >> 1) * 8 + rlo;
    const int ch  = kk * 2 + (lmat & 1);
    ldm_x4(r, tbase + (uint32_t)row * 128 + (uint32_t)((ch ^ (row & 7)) << 4));
}
__device__ __forceinline__ uint32_t packbf(float a, float b) {
    __nv_bfloat162 t = __halves2bfloat162(__float2bfloat16(a), __float2bfloat16(b));
    return *(uint32_t*)&t;
}

// ===========================================================================
// Split fp32 -> bf16 hi/lo, concatenated along K (3 segments of DM) for GEMM.
// ===========================================================================
__global__ __launch_bounds__(256)
void split_kernel(const float* __restrict__ X, bf16* __restrict__ Y, int lo_off)
{
    int idx4 = blockIdx.x * 256 + threadIdx.x;
    int r = idx4 >> 8;
    int c = (idx4 & 255) << 2;
    float4 x = *(const float4*)(X + (size_t)r * DM + c);
    float xs[4] = {x.x, x.y, x.z, x.w};
    bf16 hi[4], lo[4];
#pragma unroll
    for (int j = 0; j < 4; j++) {
        hi[j] = __float2bfloat16(xs[j]);
        lo[j] = __float2bfloat16(xs[j] - __bfloat162float(hi[j]));
    }
    const int hi2_off = (lo_off == 2048) ? 1024 : 2048;
    bf16* row = Y + (size_t)r * KSPLIT;
    __nv_bfloat162* h0 = (__nv_bfloat162*)(row + c);
    __nv_bfloat162* h1 = (__nv_bfloat162*)(row + hi2_off + c);
    __nv_bfloat162* l0 = (__nv_bfloat162*)(row + lo_off + c);
    h0[0] = __halves2bfloat162(hi[0], hi[1]); h0[1] = __halves2bfloat162(hi[2], hi[3]);
    h1[0] = __halves2bfloat162(hi[0], hi[1]); h1[1] = __halves2bfloat162(hi[2], hi[3]);
    l0[0] = __halves2bfloat162(lo[0], lo[1]); l0[1] = __halves2bfloat162(lo[2], lo[3]);
}

// Split fp32 [rows][1024] -> two bf16 arrays (hi, lo), same layout.
__global__ __launch_bounds__(256)
void split2_kernel(const float* __restrict__ X, bf16* __restrict__ Yh, bf16* __restrict__ Yl)
{
    int idx4 = blockIdx.x * 256 + threadIdx.x;
    int r = idx4 >> 8;
    int c = (idx4 & 255) << 2;
    float4 x = *(const float4*)(X + (size_t)r * DM + c);
    float xs[4] = {x.x, x.y, x.z, x.w};
    bf16 hi[4], lo[4];
#pragma unroll
    for (int j = 0; j < 4; j++) {
        hi[j] = __float2bfloat16(xs[j]);
        lo[j] = __float2bfloat16(xs[j] - __bfloat162float(hi[j]));
    }
    __nv_bfloat162* ph = (__nv_bfloat162*)(Yh + (size_t)r * DM + c);
    __nv_bfloat162* pl = (__nv_bfloat162*)(Yl + (size_t)r * DM + c);
    ph[0] = __halves2bfloat162(hi[0], hi[1]); ph[1] = __halves2bfloat162(hi[2], hi[3]);
    pl[0] = __halves2bfloat162(lo[0], lo[1]); pl[1] = __halves2bfloat162(lo[2], lo[3]);
}

// V fp32 [BS][1024] -> per-head transposed splits Vth/Vtl: [(b*16+h)*64 + d][S]
__global__ __launch_bounds__(256)
void vsplit_t_kernel(const float* __restrict__ V, bf16* __restrict__ Vth,
                     bf16* __restrict__ Vtl, int S)
{
    __shared__ float T[64][65];
    const int bh = blockIdx.x;          // b*16+h
    const int sblk = blockIdx.y;        // S/64 blocks
    const int b = bh >> 4, h = bh & 15;
    const int tid = threadIdx.x;
#pragma unroll
    for (int t = 0; t < 4; t++) {
        int idx4 = tid + t * 256;
        int s = idx4 >> 4;
        int c4 = (idx4 & 15) << 2;
        float4 v = *(const float4*)(V + (size_t)(b * S + sblk * 64 + s) * DM + h * 64 + c4);
        T[s][c4] = v.x; T[s][c4+1] = v.y; T[s][c4+2] = v.z; T[s][c4+3] = v.w;
    }
    __syncthreads();
    const int d = tid >> 2;
    const int sq = tid & 3;
    bf16* oh = Vth + (size_t)(bh * 64 + d) * S + sblk * 64 + sq * 16;
    bf16* ol = Vtl + (size_t)(bh * 64 + d) * S + sblk * 64 + sq * 16;
#pragma unroll
    for (int g = 0; g < 8; g++) {
        float v0 = T[sq*16 + 2*g][d], v1 = T[sq*16 + 2*g + 1][d];
        bf16 h0 = __float2bfloat16(v0), h1 = __float2bfloat16(v1);
        bf16 l0 = __float2bfloat16(v0 - __bfloat162float(h0));
        bf16 l1 = __float2bfloat16(v1 - __bfloat162float(h1));
        ((__nv_bfloat162*)oh)[g] = __halves2bfloat162(h0, h1);
        ((__nv_bfloat162*)ol)[g] = __halves2bfloat162(l0, l1);
    }
}

// ===========================================================================
// C[M,N] = A[M,K] * B[N,K]^T  via mma.sync bf16 (proven in R6, unchanged).
// ===========================================================================
#define G_SMEM_BYTES (2 * (128*64 + 128*64) * 2)   // 65536

__global__ __launch_bounds__(256)
void gemm_hmma(const bf16* __restrict__ A, const bf16* __restrict__ B,
               float* __restrict__ C, int M, int N, int K)
{
    extern __shared__ char smem[];
    const uint32_t sbase = smem_u32(smem);
    const int tid = threadIdx.x;
    const int wid = tid >> 5, lane = tid & 31;
    const int m0 = blockIdx.y * 128, n0 = blockIdx.x * 128;
    const int wm = (wid & 1) * 64, wn = (wid >> 1) * 32;

    const uint32_t BUF = 128*64*2*2;
    const uint32_t AOFF = 0, BOFF = 128*64*2;

    const int lc  = tid & 7;
    const int lr  = tid >> 3;
    const uint32_t lsw = (uint32_t)((lc ^ (lr & 7)) << 4);

    float acc[4][4][4];
#pragma unroll
    for (int mf = 0; mf < 4; mf++)
#pragma unroll
        for (int nf = 0; nf < 4; nf++)
#pragma unroll
            for (int j = 0; j < 4; j++) acc[mf][nf][j] = 0.f;

    const int lmat = lane >> 3, rlo = lane & 7;
    const int rA   = wm + (lmat & 1) * 8 + rlo;
    const int selA = lmat >> 1;
    const int nB   = wn + (lmat >> 1) * 8 + rlo;
    const int selB = lmat & 1;

    const int iters = K >> 6;

    {
        const bf16* Ak = A + (size_t)m0 * K;
        const bf16* Bk = B + (size_t)n0 * K;
#pragma unroll
        for (int t = 0; t < 4; t++) {
            int r = lr + t * 32;
            cp_async16(sbase + AOFF + (uint32_t)r * 128 + lsw, Ak + (size_t)r * K + lc * 8);
            cp_async16(sbase + BOFF + (uint32_t)r * 128 + lsw, Bk + (size_t)r * K + lc * 8);
        }
        cp_commit();
    }

    for (int it = 0; it < iters; ++it) {
        const int buf = it & 1;
        if (it + 1 < iters) {
            const uint32_t dA = sbase + (buf ^ 1) * BUF + AOFF;
            const uint32_t dB = sbase + (buf ^ 1) * BUF + BOFF;
            const bf16* Ak = A + (size_t)m0 * K + (it + 1) * 64;
            const bf16* Bk = B + (size_t)n0 * K + (it + 1) * 64;
#pragma unroll
            for (int t = 0; t < 4; t++) {
                int r = lr + t * 32;
                cp_async16(dA + (uint32_t)r * 128 + lsw, Ak + (size_t)r * K + lc * 8);
                cp_async16(dB + (uint32_t)r * 128 + lsw, Bk + (size_t)r * K + lc * 8);
            }
            cp_commit();
            cp_wait1();
        } else {
            cp_wait0();
        }
        __syncthreads();

        const uint32_t aS = sbase + buf * BUF + AOFF;
        const uint32_t bS = sbase + buf * BUF + BOFF;
#pragma unroll
        for (int kk = 0; kk < 4; kk++) {
            uint32_t a[4][4], b[2][4];
            const uint32_t ca = (uint32_t)(((kk * 2 + selA) ^ (rA & 7)) << 4);
#pragma unroll
            for (int mf = 0; mf < 4; mf++)
                ldm_x4(a[mf], aS + (uint32_t)(rA + mf * 16) * 128 + ca);
            const uint32_t cb = (uint32_t)(((kk * 2 + selB) ^ (nB & 7)) << 4);
#pragma unroll
            for (int nf2 = 0; nf2 < 2; nf2++)
                ldm_x4(b[nf2], bS + (uint32_t)(nB + nf2 * 16) * 128 + cb);
#pragma unroll
            for (int mf = 0; mf < 4; mf++)
#pragma unroll
                for (int nf = 0; nf < 4; nf++)
                    mma_bf16(acc[mf][nf], a[mf], b[nf >> 1] + (nf & 1) * 2);
        }
        __syncthreads();
    }

    const int er = lane >> 2, ec = (lane & 3) * 2;
#pragma unroll
    for (int mf = 0; mf < 4; mf++) {
        const int r0 = m0 + wm + mf * 16 + er;
#pragma unroll
        for (int nf = 0; nf < 4; nf++) {
            const int c = n0 + wn + nf * 8 + ec;
            *(float2*)(C + (size_t)r0 * N + c)       = make_float2(acc[mf][nf][0], acc[mf][nf][1]);
            *(float2*)(C + (size_t)(r0 + 8) * N + c) = make_float2(acc[mf][nf][2], acc[mf][nf][3]);
        }
    }
}

// ===========================================================================
// HMMA flash attention. 1 CTA = 128 q-rows of one (b,h); 8 warps x 16 rows.
// KV tiles of 64, double-buffered cp.async. 3-term bf16 split on QK and PV.
// smem: Qh(16K) Ql(16K) + 2 x [Kh|Kl|VhT|VlT](32K) = 96K dynamic.
// ===========================================================================
#define ATT_SMEM (32768 + 2*32768)

__global__ __launch_bounds__(256)
void attn_hmma(const bf16* __restrict__ Qh, const bf16* __restrict__ Ql,
               const bf16* __restrict__ Kh, const bf16* __restrict__ Kl,
               const bf16* __restrict__ Vth, const bf16* __restrict__ Vtl,
               float* __restrict__ Og, int S)
{
    extern __shared__ char smem[];
    const uint32_t base = smem_u32(smem);
    const uint32_t QHo = 0, QLo = 16384;
    const uint32_t KVo[2] = {32768u, 65536u};

    const int tid = threadIdx.x;
    const int wid = tid >> 5, lane = tid & 31;
    const int b = blockIdx.z, h = blockIdx.y;
    const int q0 = blockIdx.x * 128;
    const int bS = b * S;
    const int bh = b * NH + h;
    const float SCALE = 0.125f;        // 1/sqrt(64)
    const float L2E = 1.4426950408889634f;

    // ---- load Q tiles (hi, lo): 2048 16B-chunks
#pragma unroll
    for (int t = 0; t < 8; t++) {
        int cid = tid + t * 256;
        int tile = cid >> 10;
        int r = (cid >> 3) & 127;
        int c = cid & 7;
        const bf16* src = (tile ? Ql : Qh) + (size_t)(bS + q0 + r) * DM + h * 64 + c * 8;
        cp_async16(base + (tile ? QLo : QHo) + (uint32_t)r * 128 + (uint32_t)(((c ^ (r & 7))) << 4), src);
    }
    cp_commit();

    // ---- preload kv tile 0
    {
        const int kv0 = 0;
#pragma unroll
        for (int t = 0; t < 8; t++) {
            int cid = tid + t * 256;
            int tile = cid >> 9;
            int r = (cid >> 3) & 63;
            int c = cid & 7;
            uint32_t dst = base + KVo[0] + (uint32_t)tile * 8192 + (uint32_t)r * 128
                         + (uint32_t)((c ^ (r & 7)) << 4);
            const bf16* src;
            if      (tile == 0) src = Kh  + (size_t)(bS + kv0 + r) * DM + h * 64 + c * 8;
            else if (tile == 1) src = Kl  + (size_t)(bS + kv0 + r) * DM + h * 64 + c * 8;
            else if (tile == 2) src = Vth + (size_t)(bh * 64 + r) * S + kv0 + c * 8;
            else                src = Vtl + (size_t)(bh * 64 + r) * S + kv0 + c * 8;
            cp_async16(dst, src);
        }
        cp_commit();
    }
    cp_wait0();
    __syncthreads();

    // ---- Q fragments in registers (per warp: rows wid*16..+15, 4 k-steps)
    uint32_t qh[4][4], ql[4][4];
    const int R0 = wid * 16;
#pragma unroll
    for (int kk = 0; kk < 4; kk++) {
        ldmA(qh[kk], base + QHo, R0, kk, lane);
        ldmA(ql[kk], base + QLo, R0, kk, lane);
    }

    float m0 = -1e30f, m1 = -1e30f, l0 = 0.f, l1 = 0.f;
    float o[8][4];
#pragma unroll
    for (int j = 0; j < 8; j++)
#pragma unroll
        for (int k = 0; k < 4; k++) o[j][k] = 0.f;

    const int iters = S >> 6;
    for (int it = 0; it < iters; ++it) {
        const int buf = it & 1;
        if (it > 0) { cp_wait0(); __syncthreads(); }
        if (it + 1 < iters) {
            const int kvn = (it + 1) * 64;
#pragma unroll
            for (int t = 0; t < 8; t++) {
                int cid = tid + t * 256;
                int tile = cid >> 9;
                int r = (cid >> 3) & 63;
                int c = cid & 7;
                uint32_t dst = base + KVo[buf ^ 1] + (uint32_t)tile * 8192 + (uint32_t)r * 128
                             + (uint32_t)((c ^ (r & 7)) << 4);
                const bf16* src;
                if      (tile == 0) src = Kh  + (size_t)(bS + kvn + r) * DM + h * 64 + c * 8;
                else if (tile == 1) src = Kl  + (size_t)(bS + kvn + r) * DM + h * 64 + c * 8;
                else if (tile == 2) src = Vth + (size_t)(bh * 64 + r) * S + kvn + c * 8;
                else                src = Vtl + (size_t)(bh * 64 + r) * S + kvn + c * 8;
                cp_async16(dst, src);
            }
            cp_commit();
        }

        const uint32_t KHb = base + KVo[buf];
        const uint32_t KLb = KHb + 8192;
        const uint32_t VHb = KHb + 16384;
        const uint32_t VLb = KHb + 24576;

        // ---- S = Q' K'^T (3-term)
        float s[8][4];
#pragma unroll
        for (int j = 0; j < 8; j++)
#pragma unroll
            for (int k = 0; k < 4; k++) s[j][k] = 0.f;

#pragma unroll
        for (int kk = 0; kk < 4; kk++) {
            uint32_t bfr[4][4];
#pragma unroll
            for (int n16 = 0; n16 < 4; n16++) ldmB(bfr[n16], KHb, n16 * 16, kk, lane);
#pragma unroll
            for (int j = 0; j < 8; j++) mma_bf16(s[j], qh[kk], bfr[j >> 1] + (j & 1) * 2);
#pragma unroll
            for (int j = 0; j < 8; j++) mma_bf16(s[j], ql[kk], bfr[j >> 1] + (j & 1) * 2);
#pragma unroll
            for (int n16 = 0; n16 < 4; n16++) ldmB(bfr[n16], KLb, n16 * 16, kk, lane);
#pragma unroll
            for (int j = 0; j < 8; j++) mma_bf16(s[j], qh[kk], bfr[j >> 1] + (j & 1) * 2);
        }

        // ---- online softmax (rows r = lane>>2 and r+8, quad-local reductions)
#pragma unroll
        for (int j = 0; j < 8; j++)
#pragma unroll
            for (int k = 0; k < 4; k++) s[j][k] *= SCALE;

        float rm0 = -1e30f, rm1 = -1e30f;
#pragma unroll
        for (int j = 0; j < 8; j++) {
            rm0 = fmaxf(rm0, fmaxf(s[j][0], s[j][1]));
            rm1 = fmaxf(rm1, fmaxf(s[j][2], s[j][3]));
        }
        rm0 = fmaxf(rm0, __shfl_xor_sync(0xffffffffu, rm0, 1));
        rm0 = fmaxf(rm0, __shfl_xor_sync(0xffffffffu, rm0, 2));
        rm1 = fmaxf(rm1, __shfl_xor_sync(0xffffffffu, rm1, 1));
        rm1 = fmaxf(rm1, __shfl_xor_sync(0xffffffffu, rm1, 2));

        const float mn0 = fmaxf(m0, rm0), mn1 = fmaxf(m1, rm1);
        const float a0 = exp2f((m0 - mn0) * L2E), a1 = exp2f((m1 - mn1) * L2E);
        float rs0 = 0.f, rs1 = 0.f;
#pragma unroll
        for (int j = 0; j < 8; j++) {
            s[j][0] = exp2f((s[j][0] - mn0) * L2E);
            s[j][1] = exp2f((s[j][1] - mn0) * L2E);
            s[j][2] = exp2f((s[j][2] - mn1) * L2E);
            s[j][3] = exp2f((s[j][3] - mn1) * L2E);
            rs0 += s[j][0] + s[j][1];
            rs1 += s[j][2] + s[j][3];
        }
        rs0 += __shfl_xor_sync(0xffffffffu, rs0, 1);
        rs0 += __shfl_xor_sync(0xffffffffu, rs0, 2);
        rs1 += __shfl_xor_sync(0xffffffffu, rs1, 1);
        rs1 += __shfl_xor_sync(0xffffffffu, rs1, 2);
        l0 = l0 * a0 + rs0;  m0 = mn0;
        l1 = l1 * a1 + rs1;  m1 = mn1;
#pragma unroll
        for (int j = 0; j < 8; j++) {
            o[j][0] *= a0; o[j][1] *= a0;
            o[j][2] *= a1; o[j][3] *= a1;
        }

        // ---- O += P' V' (3-term); P hi/lo packed from accumulators in regs
#pragma unroll
        for (int kk = 0; kk < 4; kk++) {
            const int j0 = 2 * kk, j1 = 2 * kk + 1;
            float ph[8], pl[8];
            const float pv[8] = { s[j0][0], s[j0][1], s[j0][2], s[j0][3],
                                  s[j1][0], s[j1][1], s[j1][2], s[j1][3] };
#pragma unroll
            for (int e = 0; e < 8; e++) {
                ph[e] = __bfloat162float(__float2bfloat16(pv[e]));
                pl[e] = pv[e] - ph[e];
            }
            uint32_t ah[4], al[4];
            ah[0] = packbf(ph[0], ph[1]); ah[1] = packbf(ph[2], ph[3]);
            ah[2] = packbf(ph[4], ph[5]); ah[3] = packbf(ph[6], ph[7]);
            al[0] = packbf(pl[0], pl[1]); al[1] = packbf(pl[2], pl[3]);
            al[2] = packbf(pl[4], pl[5]); al[3] = packbf(pl[6], pl[7]);

            uint32_t bfr[4][4];
#pragma unroll
            for (int n16 = 0; n16 < 4; n16++) ldmB(bfr[n16], VHb, n16 * 16, kk, lane);
#pragma unroll
            for (int j = 0; j < 8; j++) mma_bf16(o[j], ah, bfr[j >> 1] + (j & 1) * 2);
#pragma unroll
            for (int j = 0; j < 8; j++) mma_bf16(o[j], al, bfr[j >> 1] + (j & 1) * 2);
#pragma unroll
            for (int n16 = 0; n16 < 4; n16++) ldmB(bfr[n16], VLb, n16 * 16, kk, lane);
#pragma unroll
            for (int j = 0; j < 8; j++) mma_bf16(o[j], ah, bfr[j >> 1] + (j & 1) * 2);
        }
    }

    // ---- writeout: O / l
    const float inv0 = 1.f / l0, inv1 = 1.f / l1;
    const int r = lane >> 2;
    const int cq = (lane & 3) * 2;
    const int row0 = bS + q0 + R0 + r;
    const int row1 = row0 + 8;
#pragma unroll
    for (int j = 0; j < 8; j++) {
        const int col = h * 64 + j * 8 + cq;
        *(float2*)(Og + (size_t)row0 * DM + col) = make_float2(o[j][0] * inv0, o[j][1] * inv0);
        *(float2*)(Og + (size_t)row1 * DM + col) = make_float2(o[j][2] * inv1, o[j][3] * inv1);
    }
}

// ===========================================================================
extern "C" void kernel_launch(void* const* d_in, const int* in_sizes, int n_in,
                              void* d_out, int out_size)
{
    const float* query = (const float*)d_in[0];
    const float* key   = (const float*)d_in[1];
    const float* value = (const float*)d_in[2];
    const float* W_q   = (const float*)d_in[3];
    const float* W_k   = (const float*)d_in[4];
    const float* W_v   = (const float*)d_in[5];
    const float* W_o   = (const float*)d_in[6];

    const int BS = in_sizes[0] / DM;   // 8192
    const int S  = S_LEN;
    const int B  = BS / S;

    float *q, *k, *v, *a;
    bf16 *asp, *wsp, *qh, *ql, *kh, *kl, *vth, *vtl;
    cudaGetSymbolAddress((void**)&q,   g_Q);
    cudaGetSymbolAddress((void**)&k,   g_K);
    cudaGetSymbolAddress((void**)&v,   g_V);
    cudaGetSymbolAddress((void**)&a,   g_A);
    cudaGetSymbolAddress((void**)&asp, g_Asp);
    cudaGetSymbolAddress((void**)&wsp, g_Wsp);
    cudaGetSymbolAddress((void**)&qh,  g_Qh);
    cudaGetSymbolAddress((void**)&ql,  g_Ql);
    cudaGetSymbolAddress((void**)&kh,  g_Kh);
    cudaGetSymbolAddress((void**)&kl,  g_Kl);
    cudaGetSymbolAddress((void**)&vth, g_Vth);
    cudaGetSymbolAddress((void**)&vtl, g_Vtl);

    cudaFuncSetAttribute(gemm_hmma, cudaFuncAttributeMaxDynamicSharedMemorySize, G_SMEM_BYTES);
    cudaFuncSetAttribute(attn_hmma, cudaFuncAttributeMaxDynamicSharedMemorySize, ATT_SMEM);

    const dim3 gg(DM/128, BS/128);
    const int actBlocks = BS;
    const int wBlocks   = DM;

    // projections
    split_kernel<<<actBlocks, 256>>>(query, asp, 2048);
    split_kernel<<<wBlocks,   256>>>(W_q,   wsp, 1024);
    gemm_hmma<<<gg, 256, G_SMEM_BYTES>>>(asp, wsp, q, BS, DM, KSPLIT);

    split_kernel<<<actBlocks, 256>>>(key, asp, 2048);
    split_kernel<<<wBlocks,   256>>>(W_k, wsp, 1024);
    gemm_hmma<<<gg, 256, G_SMEM_BYTES>>>(asp, wsp, k, BS, DM, KSPLIT);

    split_kernel<<<actBlocks, 256>>>(value, asp, 2048);
    split_kernel<<<wBlocks,   256>>>(W_v,   wsp, 1024);
    gemm_hmma<<<gg, 256, G_SMEM_BYTES>>>(asp, wsp, v, BS, DM, KSPLIT);

    // attention prep: splits + V transpose-split
    split2_kernel<<<actBlocks, 256>>>(q, qh, ql);
    split2_kernel<<<actBlocks, 256>>>(k, kh, kl);
    dim3 gv(B * NH, S / 64);
    vsplit_t_kernel<<<gv, 256>>>(v, vth, vtl, S);

    // attention (HMMA, 3-term split)
    dim3 ga(S / 128, NH, B);
    attn_hmma<<<ga, 256, ATT_SMEM>>>(qh, ql, kh, kl, vth, vtl, a, S);

    // output projection
    split_kernel<<<actBlocks, 256>>>(a,   asp, 2048);
    split_kernel<<<wBlocks,   256>>>(W_o, wsp, 1024);
    gemm_hmma<<<gg, 256, G_SMEM_BYTES>>>(asp, wsp, (float*)d_out, BS, DM, KSPLIT);
}